// round 6
// baseline (speedup 1.0000x reference)
#include <cuda_runtime.h>
#include <cstdint>

// NerfRender integrate v4c: hoisted sort predicates (bit-index fix), register-
// direct wi stores, direct sigma loads, lean rgb. One warp per ray.
// R = 65536, N = 192 (t has 193). Output: rgb [R,3] then wi [R,192].

#define NP1 193
#define NS  192
#define VR  8
#define WPB 8

#define SH_C 256          // c region starts after t/sort area
#define SH_PER_WARP 832   // 256 (t) + 576 (c)

__device__ __forceinline__ float pos_inf() { return __int_as_float(0x7f800000); }

__device__ __forceinline__ void cp_async16(uint32_t saddr, const void* gptr) {
    asm volatile("cp.async.cg.shared.global [%0], [%1], 16;\n" :: "r"(saddr), "l"(gptr));
}
__device__ __forceinline__ void cp_async_commit() {
    asm volatile("cp.async.commit_group;\n" ::: "memory");
}
__device__ __forceinline__ void cp_async_wait_all() {
    asm volatile("cp.async.wait_group 0;\n" ::: "memory");
}

// ---- precomputed lane bits -------------------------------------------------
struct LB { bool b0, b1, b2, b3, b4; };

template <int I>
__device__ __forceinline__ bool getb(const LB& lb) {
    if constexpr (I == 0)      return lb.b0;
    else if constexpr (I == 1) return lb.b1;
    else if constexpr (I == 2) return lb.b2;
    else if constexpr (I == 3) return lb.b3;
    else if constexpr (I == 4) return lb.b4;
    else return false;   // lane bit 5 of a 0..31 lane id is always 0
}

__host__ __device__ constexpr int ilog2c(int x) {
    return x <= 1 ? 0 : 1 + ilog2c(x >> 1);
}

// ---- blocked bitonic, element i = (lane<<3)|r ------------------------------
// up(i)      = ((i & K) == 0)          -> lane bit index ilog2(K)-3   (K >= 8)
// partner sel for J>=8: lane bit index ilog2(J)-3
template <int K, int J>
__device__ __forceinline__ void bstage(float (&v)[VR], const LB& lb) {
    if constexpr (J >= 8) {                    // cross-lane stage (K >= 16)
        constexpr int lj = J >> 3;
        // keepMin = (lane bit of J>>3 == lane bit of K>>3); K=256 bit is constexpr 0
        const bool keepMin = (getb<ilog2c(J) - 3>(lb) == getb<ilog2c(K) - 3>(lb));
#pragma unroll
        for (int r = 0; r < VR; r++) {
            float o = __shfl_xor_sync(0xffffffffu, v[r], lj);
            v[r] = keepMin ? fminf(v[r], o) : fmaxf(v[r], o);   // 1 FMNMX(P)
        }
    } else if constexpr (K <= 4) {             // direction compile-time in r
#pragma unroll
        for (int r = 0; r < VR; r++) {
            if ((r & J) == 0) {
                const int r2 = r | J;
                float a = v[r], b = v[r2];
                if ((r & K) == 0) { v[r] = fminf(a, b); v[r2] = fmaxf(a, b); }
                else              { v[r] = fmaxf(a, b); v[r2] = fminf(a, b); }
            }
        }
    } else if constexpr (K == 256) {           // direction constexpr (all min-up)
#pragma unroll
        for (int r = 0; r < VR; r++) {
            if ((r & J) == 0) {
                const int r2 = r | J;
                float a = v[r], b = v[r2];
                v[r] = fminf(a, b); v[r2] = fmaxf(a, b);
            }
        }
    } else {                                   // in-register, runtime direction
        constexpr int BK = ilog2c(K) - 3;      // lane bit of (K >> 3), K in [8,128]
        const bool up = !getb<BK>(lb);
#pragma unroll
        for (int r = 0; r < VR; r++) {
            if ((r & J) == 0) {
                const int r2 = r | J;
                float a = v[r], b = v[r2];
                v[r]  = up ? fminf(a, b) : fmaxf(a, b);
                v[r2] = up ? fmaxf(a, b) : fminf(a, b);
            }
        }
    }
}

template <int K, int J>
__device__ __forceinline__ void bj(float (&v)[VR], const LB& lb) {
    bstage<K, J>(v, lb);
    if constexpr (J > 1) bj<K, (J >> 1)>(v, lb);
}
template <int K>
__device__ __forceinline__ void bk(float (&v)[VR], const LB& lb) {
    bj<K, (K >> 1)>(v, lb);
    if constexpr (K < 256) bk<(K << 1)>(v, lb);
}

__global__ __launch_bounds__(WPB * 32)
void nerf_integrate_kernel(const float* __restrict__ t,
                           const float* __restrict__ sigma,
                           const float* __restrict__ c,
                           float* __restrict__ out_rgb,
                           float* __restrict__ out_wi,
                           int R) {
    const int warp = threadIdx.x >> 5;
    const int lane = threadIdx.x & 31;
    const int ray  = blockIdx.x * WPB + warp;
    if (ray >= R) return;

    __shared__ float sh[WPB][SH_PER_WARP];
    float* shw = sh[warp];

    const LB lb = { (lane & 1) != 0, (lane & 2) != 0, (lane & 4) != 0,
                    (lane & 8) != 0, (lane & 16) != 0 };

    const float* trow = t + (size_t)ray * NP1;
    const float* srow = sigma + (size_t)ray * NS;
    const float* crow = c + (size_t)ray * NS * 3;

    // ---- 1. t loads (critical path), coalesced ------------------------
    float tv[6];
#pragma unroll
    for (int r = 0; r < 6; r++) tv[r] = __ldg(trow + r * 32 + lane);
    const float t192 = (lane == 0) ? __ldg(trow + 192) : pos_inf();

    // ---- 2. prefetch c (144 float4) via cp.async ----------------------
    {
        const uint32_t shc = (uint32_t)__cvta_generic_to_shared(shw + SH_C);
        const float4* c4 = reinterpret_cast<const float4*>(crow);
#pragma unroll
        for (int e = 0; e < 4; e++)
            cp_async16(shc + (e * 32 + lane) * 16, c4 + e * 32 + lane);
        if (lane < 16)
            cp_async16(shc + (128 + lane) * 16, c4 + 128 + lane);
        cp_async_commit();
    }

    // ---- 3. stage t, reload blocked ------------------------------------
#pragma unroll
    for (int r = 0; r < 6; r++) shw[r * 32 + lane] = tv[r];
    shw[192 + lane] = t192;
    shw[224 + lane] = pos_inf();
    __syncwarp();

    float v[VR];
    {
        const float4* p = reinterpret_cast<const float4*>(shw + lane * VR);
        float4 a = p[0], b = p[1];
        v[0]=a.x; v[1]=a.y; v[2]=a.z; v[3]=a.w;
        v[4]=b.x; v[5]=b.y; v[6]=b.z; v[7]=b.w;
    }

    // ---- 4. sort 256 ----------------------------------------------------
    bk<2>(v, lb);
    const float tnext = __shfl_down_sync(0xffffffffu, v[0], 1);

    // ---- 5. sigma direct loads, sdt prefix ------------------------------
    const bool active = (lane < 24);
    float pfx[VR];
    {
        float4 s0 = make_float4(0.f,0.f,0.f,0.f), s1 = s0;
        if (active) {
            const float4* sp = reinterpret_cast<const float4*>(srow + lane * VR);
            s0 = __ldg(sp); s1 = __ldg(sp + 1);
        }
        const float sarr[VR] = {s0.x,s0.y,s0.z,s0.w,s1.x,s1.y,s1.z,s1.w};
        float run = 0.f;
#pragma unroll
        for (int e = 0; e < VR; e++) {
            float tn = (e < VR - 1) ? v[e + 1] : tnext;
            float s  = active ? sarr[e] * (tn - v[e]) : 0.f;
            run += s;
            pfx[e] = run;
        }
    }

    // ---- 6. warp exclusive scan of lane totals --------------------------
    const float tot = pfx[VR - 1];
    float inc = tot;
#pragma unroll
    for (int d = 1; d < 32; d <<= 1) {
        float y = __shfl_up_sync(0xffffffffu, inc, d);
        if (lane >= d) inc += y;
    }
    const float excl = inc - tot;

    // ---- 7. weights -------------------------------------------------------
    float w[VR];
    {
        float prevE = __expf(-excl);
#pragma unroll
        for (int e = 0; e < VR; e++) {
            float E = __expf(-(excl + pfx[e]));
            w[e] = prevE - E;
            prevE = E;
        }
    }

    // ---- 8. wi out: direct STG.128 from registers (blocked) --------------
    if (active) {
        float4* wp = reinterpret_cast<float4*>(out_wi + (size_t)ray * NS + lane * VR);
        wp[0] = make_float4(w[0], w[1], w[2], w[3]);
        wp[1] = make_float4(w[4], w[5], w[6], w[7]);
    }

    // ---- 9. rgb from shared c, compile-time channels ----------------------
    cp_async_wait_all();
    __syncwarp();

    float a0 = 0.f, a1 = 0.f, a2 = 0.f;
    if (active) {
        const float4* cp4 = reinterpret_cast<const float4*>(shw + SH_C + lane * 24);
#pragma unroll
        for (int q = 0; q < 6; q++) {
            float4 cv = cp4[q];
            const float cj[4] = {cv.x, cv.y, cv.z, cv.w};
#pragma unroll
            for (int j = 0; j < 4; j++) {
                const int k  = 4 * q + j;
                const int e  = k / 3;
                const int ch = k - 3 * e;
                const float p = w[e] * cj[j];
                if (ch == 0)      a0 += p;
                else if (ch == 1) a1 += p;
                else              a2 += p;
            }
        }
    }

    // ---- 10. reduce rgb, write ---------------------------------------------
#pragma unroll
    for (int d = 16; d > 0; d >>= 1) {
        a0 += __shfl_xor_sync(0xffffffffu, a0, d);
        a1 += __shfl_xor_sync(0xffffffffu, a1, d);
        a2 += __shfl_xor_sync(0xffffffffu, a2, d);
    }
    if (lane < 3) {
        const float val = (lane == 0) ? a0 : ((lane == 1) ? a1 : a2);
        out_rgb[(size_t)ray * 3 + lane] = val;
    }
}

extern "C" void kernel_launch(void* const* d_in, const int* in_sizes, int n_in,
                              void* d_out, int out_size) {
    const float* t     = (const float*)d_in[0];
    const float* sigma = (const float*)d_in[1];
    const float* c     = (const float*)d_in[2];

    const int R = in_sizes[0] / NP1;

    float* out_rgb = (float*)d_out;
    float* out_wi  = out_rgb + (size_t)R * 3;

    const int blocks = (R + WPB - 1) / WPB;
    nerf_integrate_kernel<<<blocks, WPB * 32>>>(t, sigma, c, out_rgb, out_wi, R);
}

// round 7
// speedup vs baseline: 1.0031x; 1.0031x over previous
#include <cuda_runtime.h>
#include <cstdint>

// NerfRender integrate v4c: hoisted sort predicates (bit-index fix), register-
// direct wi stores, direct sigma loads, lean rgb. One warp per ray.
// R = 65536, N = 192 (t has 193). Output: rgb [R,3] then wi [R,192].

#define NP1 193
#define NS  192
#define VR  8
#define WPB 8

#define SH_C 256          // c region starts after t/sort area
#define SH_PER_WARP 832   // 256 (t) + 576 (c)

__device__ __forceinline__ float pos_inf() { return __int_as_float(0x7f800000); }

__device__ __forceinline__ void cp_async16(uint32_t saddr, const void* gptr) {
    asm volatile("cp.async.cg.shared.global [%0], [%1], 16;\n" :: "r"(saddr), "l"(gptr));
}
__device__ __forceinline__ void cp_async_commit() {
    asm volatile("cp.async.commit_group;\n" ::: "memory");
}
__device__ __forceinline__ void cp_async_wait_all() {
    asm volatile("cp.async.wait_group 0;\n" ::: "memory");
}

// ---- precomputed lane bits -------------------------------------------------
struct LB { bool b0, b1, b2, b3, b4; };

template <int I>
__device__ __forceinline__ bool getb(const LB& lb) {
    if constexpr (I == 0)      return lb.b0;
    else if constexpr (I == 1) return lb.b1;
    else if constexpr (I == 2) return lb.b2;
    else if constexpr (I == 3) return lb.b3;
    else if constexpr (I == 4) return lb.b4;
    else return false;   // lane bit 5 of a 0..31 lane id is always 0
}

__host__ __device__ constexpr int ilog2c(int x) {
    return x <= 1 ? 0 : 1 + ilog2c(x >> 1);
}

// ---- blocked bitonic, element i = (lane<<3)|r ------------------------------
// up(i)      = ((i & K) == 0)          -> lane bit index ilog2(K)-3   (K >= 8)
// partner sel for J>=8: lane bit index ilog2(J)-3
template <int K, int J>
__device__ __forceinline__ void bstage(float (&v)[VR], const LB& lb) {
    if constexpr (J >= 8) {                    // cross-lane stage (K >= 16)
        constexpr int lj = J >> 3;
        // keepMin = (lane bit of J>>3 == lane bit of K>>3); K=256 bit is constexpr 0
        const bool keepMin = (getb<ilog2c(J) - 3>(lb) == getb<ilog2c(K) - 3>(lb));
#pragma unroll
        for (int r = 0; r < VR; r++) {
            float o = __shfl_xor_sync(0xffffffffu, v[r], lj);
            v[r] = keepMin ? fminf(v[r], o) : fmaxf(v[r], o);   // 1 FMNMX(P)
        }
    } else if constexpr (K <= 4) {             // direction compile-time in r
#pragma unroll
        for (int r = 0; r < VR; r++) {
            if ((r & J) == 0) {
                const int r2 = r | J;
                float a = v[r], b = v[r2];
                if ((r & K) == 0) { v[r] = fminf(a, b); v[r2] = fmaxf(a, b); }
                else              { v[r] = fmaxf(a, b); v[r2] = fminf(a, b); }
            }
        }
    } else if constexpr (K == 256) {           // direction constexpr (all min-up)
#pragma unroll
        for (int r = 0; r < VR; r++) {
            if ((r & J) == 0) {
                const int r2 = r | J;
                float a = v[r], b = v[r2];
                v[r] = fminf(a, b); v[r2] = fmaxf(a, b);
            }
        }
    } else {                                   // in-register, runtime direction
        constexpr int BK = ilog2c(K) - 3;      // lane bit of (K >> 3), K in [8,128]
        const bool up = !getb<BK>(lb);
#pragma unroll
        for (int r = 0; r < VR; r++) {
            if ((r & J) == 0) {
                const int r2 = r | J;
                float a = v[r], b = v[r2];
                v[r]  = up ? fminf(a, b) : fmaxf(a, b);
                v[r2] = up ? fmaxf(a, b) : fminf(a, b);
            }
        }
    }
}

template <int K, int J>
__device__ __forceinline__ void bj(float (&v)[VR], const LB& lb) {
    bstage<K, J>(v, lb);
    if constexpr (J > 1) bj<K, (J >> 1)>(v, lb);
}
template <int K>
__device__ __forceinline__ void bk(float (&v)[VR], const LB& lb) {
    bj<K, (K >> 1)>(v, lb);
    if constexpr (K < 256) bk<(K << 1)>(v, lb);
}

__global__ __launch_bounds__(WPB * 32)
void nerf_integrate_kernel(const float* __restrict__ t,
                           const float* __restrict__ sigma,
                           const float* __restrict__ c,
                           float* __restrict__ out_rgb,
                           float* __restrict__ out_wi,
                           int R) {
    const int warp = threadIdx.x >> 5;
    const int lane = threadIdx.x & 31;
    const int ray  = blockIdx.x * WPB + warp;
    if (ray >= R) return;

    __shared__ float sh[WPB][SH_PER_WARP];
    float* shw = sh[warp];

    const LB lb = { (lane & 1) != 0, (lane & 2) != 0, (lane & 4) != 0,
                    (lane & 8) != 0, (lane & 16) != 0 };

    const float* trow = t + (size_t)ray * NP1;
    const float* srow = sigma + (size_t)ray * NS;
    const float* crow = c + (size_t)ray * NS * 3;

    // ---- 1. t loads (critical path), coalesced ------------------------
    float tv[6];
#pragma unroll
    for (int r = 0; r < 6; r++) tv[r] = __ldg(trow + r * 32 + lane);
    const float t192 = (lane == 0) ? __ldg(trow + 192) : pos_inf();

    // ---- 2. prefetch c (144 float4) via cp.async ----------------------
    {
        const uint32_t shc = (uint32_t)__cvta_generic_to_shared(shw + SH_C);
        const float4* c4 = reinterpret_cast<const float4*>(crow);
#pragma unroll
        for (int e = 0; e < 4; e++)
            cp_async16(shc + (e * 32 + lane) * 16, c4 + e * 32 + lane);
        if (lane < 16)
            cp_async16(shc + (128 + lane) * 16, c4 + 128 + lane);
        cp_async_commit();
    }

    // ---- 3. stage t, reload blocked ------------------------------------
#pragma unroll
    for (int r = 0; r < 6; r++) shw[r * 32 + lane] = tv[r];
    shw[192 + lane] = t192;
    shw[224 + lane] = pos_inf();
    __syncwarp();

    float v[VR];
    {
        const float4* p = reinterpret_cast<const float4*>(shw + lane * VR);
        float4 a = p[0], b = p[1];
        v[0]=a.x; v[1]=a.y; v[2]=a.z; v[3]=a.w;
        v[4]=b.x; v[5]=b.y; v[6]=b.z; v[7]=b.w;
    }

    // ---- 4. sort 256 ----------------------------------------------------
    bk<2>(v, lb);
    const float tnext = __shfl_down_sync(0xffffffffu, v[0], 1);

    // ---- 5. sigma direct loads, sdt prefix ------------------------------
    const bool active = (lane < 24);
    float pfx[VR];
    {
        float4 s0 = make_float4(0.f,0.f,0.f,0.f), s1 = s0;
        if (active) {
            const float4* sp = reinterpret_cast<const float4*>(srow + lane * VR);
            s0 = __ldg(sp); s1 = __ldg(sp + 1);
        }
        const float sarr[VR] = {s0.x,s0.y,s0.z,s0.w,s1.x,s1.y,s1.z,s1.w};
        float run = 0.f;
#pragma unroll
        for (int e = 0; e < VR; e++) {
            float tn = (e < VR - 1) ? v[e + 1] : tnext;
            float s  = active ? sarr[e] * (tn - v[e]) : 0.f;
            run += s;
            pfx[e] = run;
        }
    }

    // ---- 6. warp exclusive scan of lane totals --------------------------
    const float tot = pfx[VR - 1];
    float inc = tot;
#pragma unroll
    for (int d = 1; d < 32; d <<= 1) {
        float y = __shfl_up_sync(0xffffffffu, inc, d);
        if (lane >= d) inc += y;
    }
    const float excl = inc - tot;

    // ---- 7. weights -------------------------------------------------------
    float w[VR];
    {
        float prevE = __expf(-excl);
#pragma unroll
        for (int e = 0; e < VR; e++) {
            float E = __expf(-(excl + pfx[e]));
            w[e] = prevE - E;
            prevE = E;
        }
    }

    // ---- 8. wi out: direct STG.128 from registers (blocked) --------------
    if (active) {
        float4* wp = reinterpret_cast<float4*>(out_wi + (size_t)ray * NS + lane * VR);
        wp[0] = make_float4(w[0], w[1], w[2], w[3]);
        wp[1] = make_float4(w[4], w[5], w[6], w[7]);
    }

    // ---- 9. rgb from shared c, compile-time channels ----------------------
    cp_async_wait_all();
    __syncwarp();

    float a0 = 0.f, a1 = 0.f, a2 = 0.f;
    if (active) {
        const float4* cp4 = reinterpret_cast<const float4*>(shw + SH_C + lane * 24);
#pragma unroll
        for (int q = 0; q < 6; q++) {
            float4 cv = cp4[q];
            const float cj[4] = {cv.x, cv.y, cv.z, cv.w};
#pragma unroll
            for (int j = 0; j < 4; j++) {
                const int k  = 4 * q + j;
                const int e  = k / 3;
                const int ch = k - 3 * e;
                const float p = w[e] * cj[j];
                if (ch == 0)      a0 += p;
                else if (ch == 1) a1 += p;
                else              a2 += p;
            }
        }
    }

    // ---- 10. reduce rgb, write ---------------------------------------------
#pragma unroll
    for (int d = 16; d > 0; d >>= 1) {
        a0 += __shfl_xor_sync(0xffffffffu, a0, d);
        a1 += __shfl_xor_sync(0xffffffffu, a1, d);
        a2 += __shfl_xor_sync(0xffffffffu, a2, d);
    }
    if (lane < 3) {
        const float val = (lane == 0) ? a0 : ((lane == 1) ? a1 : a2);
        out_rgb[(size_t)ray * 3 + lane] = val;
    }
}

extern "C" void kernel_launch(void* const* d_in, const int* in_sizes, int n_in,
                              void* d_out, int out_size) {
    const float* t     = (const float*)d_in[0];
    const float* sigma = (const float*)d_in[1];
    const float* c     = (const float*)d_in[2];

    const int R = in_sizes[0] / NP1;

    float* out_rgb = (float*)d_out;
    float* out_wi  = out_rgb + (size_t)R * 3;

    const int blocks = (R + WPB - 1) / WPB;
    nerf_integrate_kernel<<<blocks, WPB * 32>>>(t, sigma, c, out_rgb, out_wi, R);
}

// round 9
// speedup vs baseline: 1.2515x; 1.2476x over previous
#include <cuda_runtime.h>
#include <cstdint>

// NerfRender integrate v6: integer-domain reversal-form bitonic sort.
// In-register comparators: IMNMX.U32 (ALU) + exact max recovery via 2x IMAD
// (FMA pipe). Cross-lane: predicated IMNMX. One warp per ray.
// R = 65536, N = 192 (t has 193). Output: rgb [R,3] then wi [R,192].

#define NP1 193
#define NS  192
#define VR  8
#define WPB 8
#define SH_C 256
#define SH_PER_WARP 832
#define FULL 0xffffffffu
#define PINF_BITS 0x7f800000u

typedef uint32_t u32;

__device__ __forceinline__ void cp_async16(u32 saddr, const void* gptr) {
    asm volatile("cp.async.cg.shared.global [%0], [%1], 16;\n" :: "r"(saddr), "l"(gptr));
}
__device__ __forceinline__ void cp_async_commit() {
    asm volatile("cp.async.commit_group;\n" ::: "memory");
}
__device__ __forceinline__ void cp_async_wait_all() {
    asm volatile("cp.async.wait_group 0;\n" ::: "memory");
}

// forced IMAD (fma pipe): d = a*b + c (mod 2^32)
__device__ __forceinline__ u32 madlo(u32 a, u32 b, u32 c) {
    u32 d; asm("mad.lo.u32 %0, %1, %2, %3;" : "=r"(d) : "r"(a), "r"(b), "r"(c));
    return d;
}

// ---- lane bits ---------------------------------------------------------------
struct LB { bool b0, b1, b2, b3, b4; };
template <int I>
__device__ __forceinline__ bool getb(const LB& lb) {
    if constexpr (I == 0)      return lb.b0;
    else if constexpr (I == 1) return lb.b1;
    else if constexpr (I == 2) return lb.b2;
    else if constexpr (I == 3) return lb.b3;
    else                       return lb.b4;
}

// ---- comparator, min to a, exact max via FMA pipe ------------------------------
__device__ __forceinline__ void ce(u32& a, u32& b, u32 one, u32 m1) {
    u32 mn = min(a, b);             // IMNMX.U32 (ALU)
    u32 s  = madlo(a, one, b);      // IMAD (FMA): a + b
    b = madlo(mn, m1, s);           // IMAD (FMA): s - mn  == max, exact
    a = mn;
}

// in-register stages (compile-time min-down, reversal form)
#define CE(x, y) ce(v[x], v[y], one, m1)
__device__ __forceinline__ void stage_J1(u32 (&v)[VR], u32 one, u32 m1) {
    CE(0,1); CE(2,3); CE(4,5); CE(6,7);
}
__device__ __forceinline__ void stage_J2(u32 (&v)[VR], u32 one, u32 m1) {
    CE(0,2); CE(1,3); CE(4,6); CE(5,7);
}
__device__ __forceinline__ void stage_J4(u32 (&v)[VR], u32 one, u32 m1) {
    CE(0,4); CE(1,5); CE(2,6); CE(3,7);
}
__device__ __forceinline__ void stage_rev4(u32 (&v)[VR], u32 one, u32 m1) {
    CE(0,3); CE(1,2); CE(4,7); CE(5,6);
}
__device__ __forceinline__ void stage_rev8(u32 (&v)[VR], u32 one, u32 m1) {
    CE(0,7); CE(1,6); CE(2,5); CE(3,4);
}
#undef CE

// cross-lane reversal: partner lane^LMASK, partner reg 7-r; keepMin = !laneBit(KB)
template <int LMASK, int KB>
__device__ __forceinline__ void rev_cross(u32 (&v)[VR], const LB& lb) {
    u32 o[VR];
#pragma unroll
    for (int r = 0; r < VR; r++) o[r] = __shfl_xor_sync(FULL, v[7 - r], LMASK);
    const bool keep = !getb<KB>(lb);
#pragma unroll
    for (int r = 0; r < VR; r++)
        v[r] = keep ? min(v[r], o[r]) : max(v[r], o[r]);   // 1 IMNMX(P)
}
// cross-lane halving: partner lane^LJ, same reg; keepMin = !laneBit(log2 LJ)
template <int LJ, int KB>
__device__ __forceinline__ void halv_cross(u32 (&v)[VR], const LB& lb) {
    u32 o[VR];
#pragma unroll
    for (int r = 0; r < VR; r++) o[r] = __shfl_xor_sync(FULL, v[r], LJ);
    const bool keep = !getb<KB>(lb);
#pragma unroll
    for (int r = 0; r < VR; r++)
        v[r] = keep ? min(v[r], o[r]) : max(v[r], o[r]);
}

__global__ __launch_bounds__(WPB * 32)
void nerf_integrate_kernel(const float* __restrict__ t,
                           const float* __restrict__ sigma,
                           const float* __restrict__ c,
                           float* __restrict__ out_rgb,
                           float* __restrict__ out_wi,
                           int R) {
    const int warp = threadIdx.x >> 5;
    const int lane = threadIdx.x & 31;
    const int ray  = blockIdx.x * WPB + warp;
    if (ray >= R) return;

    __shared__ u32 sh[WPB][SH_PER_WARP];
    u32* shw = sh[warp];

    const LB lb = { (lane & 1) != 0, (lane & 2) != 0, (lane & 4) != 0,
                    (lane & 8) != 0, (lane & 16) != 0 };

    // opaque constants so ptxas keeps mad.lo as IMAD (fma pipe)
    const u32 one = __shfl_sync(FULL, 1u, 0);
    const u32 m1  = 0u - one;

    const u32*   trow = reinterpret_cast<const u32*>(t) + (size_t)ray * NP1;
    const float* srow = sigma + (size_t)ray * NS;
    const float* crow = c + (size_t)ray * NS * 3;

    // ---- 1. t loads (bit patterns), coalesced ---------------------------
    u32 tv[6];
#pragma unroll
    for (int r = 0; r < 6; r++) tv[r] = __ldg(trow + r * 32 + lane);
    const u32 t192 = (lane == 0) ? __ldg(trow + 192) : PINF_BITS;

    // ---- 2. prefetch c via cp.async ---------------------------------------
    {
        const u32 shc = (u32)__cvta_generic_to_shared(shw + SH_C);
        const float4* c4 = reinterpret_cast<const float4*>(crow);
#pragma unroll
        for (int e = 0; e < 4; e++)
            cp_async16(shc + (e * 32 + lane) * 16, c4 + e * 32 + lane);
        if (lane < 16)
            cp_async16(shc + (128 + lane) * 16, c4 + 128 + lane);
        cp_async_commit();
    }

    // ---- 3. stage t, reload blocked -----------------------------------------
#pragma unroll
    for (int r = 0; r < 6; r++) shw[r * 32 + lane] = tv[r];
    shw[192 + lane] = t192;
    shw[224 + lane] = PINF_BITS;
    __syncwarp();

    u32 v[VR];
    {
        const uint4* p = reinterpret_cast<const uint4*>(shw + lane * VR);
        uint4 a = p[0], b = p[1];
        v[0]=a.x; v[1]=a.y; v[2]=a.z; v[3]=a.w;
        v[4]=b.x; v[5]=b.y; v[6]=b.z; v[7]=b.w;
    }

    // ---- 4. reversal-form bitonic sort (uint domain) ------------------------
    // m=2
    stage_J1(v, one, m1);
    // m=4
    stage_rev4(v, one, m1); stage_J1(v, one, m1);
    // m=8
    stage_rev8(v, one, m1); stage_J2(v, one, m1); stage_J1(v, one, m1);
    // m=16
    rev_cross<1, 0>(v, lb);
    stage_J4(v, one, m1); stage_J2(v, one, m1); stage_J1(v, one, m1);
    // m=32
    rev_cross<3, 1>(v, lb);
    halv_cross<1, 0>(v, lb);
    stage_J4(v, one, m1); stage_J2(v, one, m1); stage_J1(v, one, m1);
    // m=64
    rev_cross<7, 2>(v, lb);
    halv_cross<2, 1>(v, lb); halv_cross<1, 0>(v, lb);
    stage_J4(v, one, m1); stage_J2(v, one, m1); stage_J1(v, one, m1);
    // m=128
    rev_cross<15, 3>(v, lb);
    halv_cross<4, 2>(v, lb); halv_cross<2, 1>(v, lb); halv_cross<1, 0>(v, lb);
    stage_J4(v, one, m1); stage_J2(v, one, m1); stage_J1(v, one, m1);
    // m=256
    rev_cross<31, 4>(v, lb);
    halv_cross<8, 3>(v, lb); halv_cross<4, 2>(v, lb);
    halv_cross<2, 1>(v, lb); halv_cross<1, 0>(v, lb);
    stage_J4(v, one, m1); stage_J2(v, one, m1); stage_J1(v, one, m1);

    // ---- 5. back to float, boundary, sigma, sdt prefix -----------------------
    float f[VR];
#pragma unroll
    for (int e = 0; e < VR; e++) f[e] = __uint_as_float(v[e]);

    const float tnext = __uint_as_float(__shfl_down_sync(FULL, v[0], 1));
    const bool active = (lane < 24);

    float pfx[VR];
    {
        float4 s0 = make_float4(0.f,0.f,0.f,0.f), s1 = s0;
        if (active) {
            const float4* sp = reinterpret_cast<const float4*>(srow + lane * VR);
            s0 = __ldg(sp); s1 = __ldg(sp + 1);
        }
        const float sarr[VR] = {s0.x,s0.y,s0.z,s0.w,s1.x,s1.y,s1.z,s1.w};
        float run = 0.f;
#pragma unroll
        for (int e = 0; e < VR; e++) {
            float tn = (e < VR - 1) ? f[e + 1] : tnext;
            float s  = active ? sarr[e] * (tn - f[e]) : 0.f;
            run += s;
            pfx[e] = run;
        }
    }

    // ---- 6. warp exclusive scan ------------------------------------------------
    const float tot = pfx[VR - 1];
    float inc = tot;
#pragma unroll
    for (int d = 1; d < 32; d <<= 1) {
        float y = __shfl_up_sync(FULL, inc, d);
        if (lane >= d) inc += y;
    }
    const float excl = inc - tot;

    // ---- 7. weights ---------------------------------------------------------------
    float w[VR];
    {
        float prevE = __expf(-excl);
#pragma unroll
        for (int e = 0; e < VR; e++) {
            float E = __expf(-(excl + pfx[e]));
            w[e] = prevE - E;
            prevE = E;
        }
    }

    // ---- 8. wi out: direct STG.128 (blocked) ----------------------------------------
    if (active) {
        float4* wp = reinterpret_cast<float4*>(out_wi + (size_t)ray * NS + lane * VR);
        wp[0] = make_float4(w[0], w[1], w[2], w[3]);
        wp[1] = make_float4(w[4], w[5], w[6], w[7]);
    }

    // ---- 9. rgb from shared c, compile-time channels ---------------------------------
    cp_async_wait_all();
    __syncwarp();

    float a0 = 0.f, a1 = 0.f, a2 = 0.f;
    if (active) {
        const float4* cp4 = reinterpret_cast<const float4*>(
            reinterpret_cast<const float*>(shw + SH_C) + lane * 24);
#pragma unroll
        for (int q = 0; q < 6; q++) {
            float4 cv = cp4[q];
            const float cj[4] = {cv.x, cv.y, cv.z, cv.w};
#pragma unroll
            for (int j = 0; j < 4; j++) {
                const int k  = 4 * q + j;
                const int e  = k / 3;
                const int ch = k - 3 * e;
                const float p = w[e] * cj[j];
                if (ch == 0)      a0 += p;
                else if (ch == 1) a1 += p;
                else              a2 += p;
            }
        }
    }

    // ---- 10. reduce rgb, write ---------------------------------------------------------
#pragma unroll
    for (int d = 16; d > 0; d >>= 1) {
        a0 += __shfl_xor_sync(FULL, a0, d);
        a1 += __shfl_xor_sync(FULL, a1, d);
        a2 += __shfl_xor_sync(FULL, a2, d);
    }
    if (lane < 3) {
        const float val = (lane == 0) ? a0 : ((lane == 1) ? a1 : a2);
        out_rgb[(size_t)ray * 3 + lane] = val;
    }
}

extern "C" void kernel_launch(void* const* d_in, const int* in_sizes, int n_in,
                              void* d_out, int out_size) {
    const float* t     = (const float*)d_in[0];
    const float* sigma = (const float*)d_in[1];
    const float* c     = (const float*)d_in[2];

    const int R = in_sizes[0] / NP1;

    float* out_rgb = (float*)d_out;
    float* out_wi  = out_rgb + (size_t)R * 3;

    const int blocks = (R + WPB - 1) / WPB;
    nerf_integrate_kernel<<<blocks, WPB * 32>>>(t, sigma, c, out_rgb, out_wi, R);
}